// round 9
// baseline (speedup 1.0000x reference)
#include <cuda_runtime.h>
#include <math.h>

#define BB 512
#define CC 256
#define NW 8                 // 256 concepts / 32 bits
#define TEMP_INV (1.0f/0.07f)
#define GRID 512
#define NWORK 64             // last-arriving worker blocks (8 rows each, warp-per-row)
#define THRESH (GRID - NWORK)

// ---- persistent scratch (no allocation allowed) ----
__device__ float    g_clip[2*BB];    // per-row (lse - diag): img [0..511], txt [512..1023]
__device__ float    g_ccl [2*BB];    // per-row bce sum [0..511], mask sum [512..1023]
__device__ float    g_kl  [BB];      // per-row KL term
__device__ unsigned g_bits[BB*NW];   // binary concept bitmasks (row-major [row][word])
__device__ int      g_cnt [BB];      // per-row positive-concept popcount
__device__ unsigned g_c1  = 0;       // phase-1 ticket counter (atomicInc wraps -> replay-safe)
__device__ unsigned g_gen = 0;       // monotonic generation flag (release for workers)
__device__ unsigned g_c2  = 0;       // worker completion counter (wraps)

// ---------- deterministic block reductions (256 threads) ----------
__device__ __forceinline__ void blockMax2(float& a, float& b) {
    __shared__ float sh[2][8];
    int tid = threadIdx.x;
    #pragma unroll
    for (int o = 16; o > 0; o >>= 1) {
        a = fmaxf(a, __shfl_down_sync(0xffffffffu, a, o));
        b = fmaxf(b, __shfl_down_sync(0xffffffffu, b, o));
    }
    if ((tid & 31) == 0) { int w = tid >> 5; sh[0][w] = a; sh[1][w] = b; }
    __syncthreads();
    float ra = sh[0][0], rb = sh[1][0];
    #pragma unroll
    for (int w = 1; w < 8; w++) { ra = fmaxf(ra, sh[0][w]); rb = fmaxf(rb, sh[1][w]); }
    a = ra; b = rb;
}

__device__ __forceinline__ void blockSum5(float& a, float& b, float& c, float& d, float& e) {
    __shared__ float sh[5][8];
    int tid = threadIdx.x;
    #pragma unroll
    for (int o = 16; o > 0; o >>= 1) {
        a += __shfl_down_sync(0xffffffffu, a, o);
        b += __shfl_down_sync(0xffffffffu, b, o);
        c += __shfl_down_sync(0xffffffffu, c, o);
        d += __shfl_down_sync(0xffffffffu, d, o);
        e += __shfl_down_sync(0xffffffffu, e, o);
    }
    if ((tid & 31) == 0) {
        int w = tid >> 5;
        sh[0][w] = a; sh[1][w] = b; sh[2][w] = c; sh[3][w] = d; sh[4][w] = e;
    }
    __syncthreads();
    float ra = 0.f, rb = 0.f, rc = 0.f, rd = 0.f, re = 0.f;
    #pragma unroll
    for (int w = 0; w < 8; w++) {
        ra += sh[0][w]; rb += sh[1][w]; rc += sh[2][w]; rd += sh[3][w]; re += sh[4][w];
    }
    a = ra; b = rb; c = rc; d = rd; e = re;
}

__device__ __forceinline__ void blockSum4(float& a, float& b, float& c, float& d) {
    __shared__ float sh[4][8];
    int tid = threadIdx.x;
    #pragma unroll
    for (int o = 16; o > 0; o >>= 1) {
        a += __shfl_down_sync(0xffffffffu, a, o);
        b += __shfl_down_sync(0xffffffffu, b, o);
        c += __shfl_down_sync(0xffffffffu, c, o);
        d += __shfl_down_sync(0xffffffffu, d, o);
    }
    if ((tid & 31) == 0) { int w = tid >> 5; sh[0][w] = a; sh[1][w] = b; sh[2][w] = c; sh[3][w] = d; }
    __syncthreads();
    float ra = 0.f, rb = 0.f, rc = 0.f, rd = 0.f;
    #pragma unroll
    for (int w = 0; w < 8; w++) { ra += sh[0][w]; rb += sh[1][w]; rc += sh[2][w]; rd += sh[3][w]; }
    a = ra; b = rb; c = rc; d = rd;
}

__global__ void __launch_bounds__(256, 4)
cca_kernel(const float* __restrict__ img,
           const float* __restrict__ txt,
           const float* __restrict__ cl,
           const float* __restrict__ cis,
           const int*   __restrict__ mc,
           float* __restrict__ out) {
    const int b   = blockIdx.x;
    const int tid = threadIdx.x;

    // ================= phase 1: per-row BCE + bitmask + CLIP lse =================
    {
        int   m  = mc[(size_t)b * CC + tid];
        float x  = cl[(size_t)b * CC + tid];
        const float* ri = img + (size_t)b * BB;
        const float* rt = txt + (size_t)b * BB;
        float i0 = ri[tid], i1 = ri[tid + 256];
        float t0 = rt[tid], t1 = rt[tid + 256];

        float mask = (m != -1) ? 1.f : 0.f;
        float tgt  = (m > 0)   ? 1.f : 0.f;
        float la   = (x > 0.f) ? (x + log1pf(__expf(-x))) : log1pf(__expf(x));
        float loss = (la - x * tgt) * mask;
        unsigned ball = __ballot_sync(0xffffffffu, m > 0);
        if ((tid & 31) == 0) g_bits[b * NW + (tid >> 5)] = ball;

        float mi = fmaxf(i0, i1), mt = fmaxf(t0, t1);
        blockMax2(mi, mt);
        float si = __expf(i0 - mi) + __expf(i1 - mi);
        float st = __expf(t0 - mt) + __expf(t1 - mt);
        float ls = loss, ms = mask, pc = tgt;
        blockSum5(si, st, ls, ms, pc);
        if (tid == 0) {
            g_clip[b]      = mi + logf(si) - ri[b];
            g_clip[BB + b] = mt + logf(st) - rt[b];
            g_ccl[b]       = ls;
            g_ccl[BB + b]  = ms;
            g_cnt[b]       = (int)pc;
        }
    }

    // ============ arrival: last NWORK blocks become KL workers ============
    __shared__ int widx_sh;
    __syncthreads();
    if (tid == 0) {
        __threadfence();                                   // release phase-1 writes
        unsigned gen = *(volatile unsigned*)&g_gen;        // snapshot BEFORE arriving
        unsigned t = atomicInc(&g_c1, GRID - 1);           // wraps -> replay-safe
        if (t == GRID - 1) {
            __threadfence();
            atomicAdd(&g_gen, 1u);                         // release all workers
            widx_sh = (int)t - THRESH;
        } else if (t >= THRESH) {
            volatile unsigned* p = &g_gen;
            while (*p == gen) {}                           // short spin: arrival skew only
            widx_sh = (int)t - THRESH;
        } else {
            widx_sh = -1;
        }
        __threadfence();                                   // acquire other blocks' phase-1 writes
    }
    __syncthreads();
    const int widx = widx_sh;
    if (widx < 0) return;

    // ================= phase 2: warp-per-row Jaccard -> KL =================
    {
        const int wid  = tid >> 5;
        const int lane = tid & 31;
        const int row  = widx * 8 + wid;                   // 64 blocks * 8 warps = 512 rows
        const uint4* bits4 = (const uint4*)g_bits;

        uint4 a0 = bits4[2 * row], a1 = bits4[2 * row + 1];   // broadcast within warp
        int   cnti = g_cnt[row];
        float maxs = (cnti > 0) ? TEMP_INV : 0.f;

        // load 16 cis values, find row max (deterministic shfl tree)
        float cv[16];
        float maxc = -3.402823e38f;
        #pragma unroll
        for (int k = 0; k < 16; k++) {
            cv[k] = cis[(size_t)row * BB + lane + k * 32];
            maxc = fmaxf(maxc, cv[k]);
        }
        #pragma unroll
        for (int o = 16; o > 0; o >>= 1)
            maxc = fmaxf(maxc, __shfl_xor_sync(0xffffffffu, maxc, o));

        float es = 0.f, num = 0.f, ec = 0.f;
        #pragma unroll
        for (int k = 0; k < 16; k++) {
            int j = lane + k * 32;
            uint4 p0 = bits4[2 * j], p1 = bits4[2 * j + 1];
            int inter = __popc(a0.x & p0.x) + __popc(a0.y & p0.y)
                      + __popc(a0.z & p0.z) + __popc(a0.w & p0.w)
                      + __popc(a1.x & p1.x) + __popc(a1.y & p1.y)
                      + __popc(a1.z & p1.z) + __popc(a1.w & p1.w);
            int   uni = cnti + g_cnt[j] - inter;
            float sim = (uni > 0) ? (float)inter / (float)uni : 0.f;
            float s   = sim * TEMP_INV;
            float e   = __expf(s - maxs);
            es  += e;
            num += e * (s - cv[k]);
            ec  += __expf(cv[k] - maxc);
        }
        #pragma unroll
        for (int o = 16; o > 0; o >>= 1) {
            es  += __shfl_down_sync(0xffffffffu, es,  o);
            ec  += __shfl_down_sync(0xffffffffu, ec,  o);
            num += __shfl_down_sync(0xffffffffu, num, o);
        }
        if (lane == 0)
            g_kl[row] = num / es - maxs - logf(es) + maxc + logf(ec);
    }

    // ============ worker completion: last of 64 folds -> out ============
    __shared__ bool is_last;
    __syncthreads();
    if (tid == 0) {
        __threadfence();
        unsigned t2 = atomicInc(&g_c2, NWORK - 1);         // wraps -> replay-safe
        is_last = (t2 == NWORK - 1);
    }
    __syncthreads();
    if (is_last) {
        __threadfence();                                   // acquire other workers' g_kl
        float cs = 0.f, ls = 0.f, ms = 0.f, ks = 0.f;
        #pragma unroll
        for (int k = 0; k < 4; k++) cs += __ldcg(&g_clip[tid + k * 256]);
        #pragma unroll
        for (int k = 0; k < 2; k++) {
            ls += __ldcg(&g_ccl[tid + k * 256]);
            ms += __ldcg(&g_ccl[BB + tid + k * 256]);
            ks += __ldcg(&g_kl[tid + k * 256]);
        }
        blockSum4(cs, ls, ms, ks);
        if (tid == 0) {
            float clip_loss = cs / (2.f * BB);
            float bce_loss  = ls / (ms + 1e-8f);
            float kl_loss   = ks / (float)BB;
            out[0] = clip_loss + 0.5f * bce_loss + 0.3f * kl_loss;
        }
    }
}

extern "C" void kernel_launch(void* const* d_in, const int* in_sizes, int n_in,
                              void* d_out, int out_size) {
    const float* img = (const float*)d_in[0];   // logits_per_image [512,512]
    const float* txt = (const float*)d_in[1];   // logits_per_text  [512,512]
    const float* cl  = (const float*)d_in[2];   // concepts_logits  [512,256]
    const float* cis = (const float*)d_in[3];   // concepts_image_similarity [512,512]
    const int*   mc  = (const int*)d_in[4];     // medical_concepts [512,256]
    float* out = (float*)d_out;

    cca_kernel<<<GRID, 256>>>(img, txt, cl, cis, mc, out);
}

// round 10
// speedup vs baseline: 1.1274x; 1.1274x over previous
#include <cuda_runtime.h>
#include <math.h>

#define BB 512
#define CC 256
#define NW 8                 // 256 concepts / 32 bits
#define TEMP_INV (1.0f/0.07f)
#define GRID1 512            // k1: block-per-row
#define GRID2 64             // k2: 64 blocks x 8 warps = 512 warp-rows

// ---- persistent scratch (no allocation allowed) ----
__device__ float    g_clip[2*BB];    // per-row (lse - diag): img [0..511], txt [512..1023]
__device__ float    g_ccl [2*BB];    // per-row bce sum [0..511], mask sum [512..1023]
__device__ float    g_kl  [BB];      // per-row KL term
__device__ unsigned g_bits[BB*NW];   // binary concept bitmasks (row-major [row][word])
__device__ int      g_cnt [BB];      // per-row positive-concept popcount
__device__ unsigned g_done = 0;      // k2 completion counter (atomicInc wraps -> replay-safe)

// ---------- deterministic block reductions (256 threads) ----------
__device__ __forceinline__ void blockMax2(float& a, float& b) {
    __shared__ float sh[2][8];
    int tid = threadIdx.x;
    #pragma unroll
    for (int o = 16; o > 0; o >>= 1) {
        a = fmaxf(a, __shfl_down_sync(0xffffffffu, a, o));
        b = fmaxf(b, __shfl_down_sync(0xffffffffu, b, o));
    }
    if ((tid & 31) == 0) { int w = tid >> 5; sh[0][w] = a; sh[1][w] = b; }
    __syncthreads();
    float ra = sh[0][0], rb = sh[1][0];
    #pragma unroll
    for (int w = 1; w < 8; w++) { ra = fmaxf(ra, sh[0][w]); rb = fmaxf(rb, sh[1][w]); }
    a = ra; b = rb;
}

__device__ __forceinline__ void blockSum5(float& a, float& b, float& c, float& d, float& e) {
    __shared__ float sh[5][8];
    int tid = threadIdx.x;
    #pragma unroll
    for (int o = 16; o > 0; o >>= 1) {
        a += __shfl_down_sync(0xffffffffu, a, o);
        b += __shfl_down_sync(0xffffffffu, b, o);
        c += __shfl_down_sync(0xffffffffu, c, o);
        d += __shfl_down_sync(0xffffffffu, d, o);
        e += __shfl_down_sync(0xffffffffu, e, o);
    }
    if ((tid & 31) == 0) {
        int w = tid >> 5;
        sh[0][w] = a; sh[1][w] = b; sh[2][w] = c; sh[3][w] = d; sh[4][w] = e;
    }
    __syncthreads();
    float ra = 0.f, rb = 0.f, rc = 0.f, rd = 0.f, re = 0.f;
    #pragma unroll
    for (int w = 0; w < 8; w++) {
        ra += sh[0][w]; rb += sh[1][w]; rc += sh[2][w]; rd += sh[3][w]; re += sh[4][w];
    }
    a = ra; b = rb; c = rc; d = rd; e = re;
}

__device__ __forceinline__ void blockSum4(float& a, float& b, float& c, float& d) {
    __shared__ float sh[4][8];
    int tid = threadIdx.x;
    #pragma unroll
    for (int o = 16; o > 0; o >>= 1) {
        a += __shfl_down_sync(0xffffffffu, a, o);
        b += __shfl_down_sync(0xffffffffu, b, o);
        c += __shfl_down_sync(0xffffffffu, c, o);
        d += __shfl_down_sync(0xffffffffu, d, o);
    }
    if ((tid & 31) == 0) { int w = tid >> 5; sh[0][w] = a; sh[1][w] = b; sh[2][w] = c; sh[3][w] = d; }
    __syncthreads();
    float ra = 0.f, rb = 0.f, rc = 0.f, rd = 0.f;
    #pragma unroll
    for (int w = 0; w < 8; w++) { ra += sh[0][w]; rb += sh[1][w]; rc += sh[2][w]; rd += sh[3][w]; }
    a = ra; b = rb; c = rc; d = rd;
}

// =======================================================================
// K1: per-row BCE + bitmasks + CLIP lse (img+txt). No atomics.
// =======================================================================
__global__ void __launch_bounds__(256, 4)
k1_rows(const float* __restrict__ img,
        const float* __restrict__ txt,
        const float* __restrict__ cl,
        const int*   __restrict__ mc) {
    const int b   = blockIdx.x;
    const int tid = threadIdx.x;

    // issue all global loads up front
    int   m  = mc[(size_t)b * CC + tid];
    float x  = cl[(size_t)b * CC + tid];
    const float* ri = img + (size_t)b * BB;
    const float* rt = txt + (size_t)b * BB;
    float i0 = ri[tid], i1 = ri[tid + 256];
    float t0 = rt[tid], t1 = rt[tid + 256];

    float mask = (m != -1) ? 1.f : 0.f;
    float tgt  = (m > 0)   ? 1.f : 0.f;
    float la   = (x > 0.f) ? (x + log1pf(__expf(-x))) : log1pf(__expf(x));
    float loss = (la - x * tgt) * mask;
    unsigned ball = __ballot_sync(0xffffffffu, m > 0);
    if ((tid & 31) == 0) g_bits[b * NW + (tid >> 5)] = ball;

    float mi = fmaxf(i0, i1), mt = fmaxf(t0, t1);
    blockMax2(mi, mt);
    float si = __expf(i0 - mi) + __expf(i1 - mi);
    float st = __expf(t0 - mt) + __expf(t1 - mt);
    float ls = loss, ms = mask, pc = tgt;
    blockSum5(si, st, ls, ms, pc);
    if (tid == 0) {
        g_clip[b]      = mi + logf(si) - ri[b];
        g_clip[BB + b] = mt + logf(st) - rt[b];
        g_ccl[b]       = ls;
        g_ccl[BB + b]  = ms;
        g_cnt[b]       = (int)pc;
    }
}

// =======================================================================
// K2: warp-per-row Jaccard -> KL (64 blocks x 8 warps); last block -> out
// =======================================================================
__global__ void __launch_bounds__(256, 4)
k2_kl(const float* __restrict__ cis, float* __restrict__ out) {
    const int b    = blockIdx.x;      // 0..63
    const int tid  = threadIdx.x;
    const int wid  = tid >> 5;
    const int lane = tid & 31;
    const int row  = b * 8 + wid;     // 512 warp-rows
    const uint4* bits4 = (const uint4*)g_bits;

    // own row's mask (warp-broadcast loads) + count
    uint4 a0 = bits4[2 * row], a1 = bits4[2 * row + 1];
    int   cnti = g_cnt[row];
    float maxs = (cnti > 0) ? TEMP_INV : 0.f;   // sim(i,i)=1 when row nonempty

    // 16 cis values per lane (coalesced), row max via shfl tree
    float cv[16];
    float maxc = -3.402823e38f;
    #pragma unroll
    for (int k = 0; k < 16; k++) {
        cv[k] = cis[(size_t)row * BB + lane + k * 32];
        maxc = fmaxf(maxc, cv[k]);
    }
    #pragma unroll
    for (int o = 16; o > 0; o >>= 1)
        maxc = fmaxf(maxc, __shfl_xor_sync(0xffffffffu, maxc, o));

    float es = 0.f, num = 0.f, ec = 0.f;
    #pragma unroll
    for (int k = 0; k < 16; k++) {
        int j = lane + k * 32;
        uint4 p0 = bits4[2 * j], p1 = bits4[2 * j + 1];
        int inter = __popc(a0.x & p0.x) + __popc(a0.y & p0.y)
                  + __popc(a0.z & p0.z) + __popc(a0.w & p0.w)
                  + __popc(a1.x & p1.x) + __popc(a1.y & p1.y)
                  + __popc(a1.z & p1.z) + __popc(a1.w & p1.w);
        int   uni = cnti + g_cnt[j] - inter;
        float sim = (uni > 0) ? (float)inter / (float)uni : 0.f;
        float s   = sim * TEMP_INV;
        float e   = __expf(s - maxs);
        es  += e;
        num += e * (s - cv[k]);
        ec  += __expf(cv[k] - maxc);
    }
    #pragma unroll
    for (int o = 16; o > 0; o >>= 1) {
        es  += __shfl_down_sync(0xffffffffu, es,  o);
        ec  += __shfl_down_sync(0xffffffffu, ec,  o);
        num += __shfl_down_sync(0xffffffffu, num, o);
    }
    if (lane == 0)
        g_kl[row] = num / es - maxs - logf(es) + maxc + logf(ec);

    // -------- completion: last of 64 blocks folds everything -> out --------
    __shared__ bool is_last;
    __syncthreads();
    if (tid == 0) {
        __threadfence();
        unsigned t = atomicInc(&g_done, GRID2 - 1);   // wraps to 0 -> replay-safe
        is_last = (t == GRID2 - 1);
    }
    __syncthreads();
    if (is_last) {
        __threadfence();   // acquire other blocks' g_kl writes
        float cs = 0.f, ls = 0.f, ms = 0.f, ks = 0.f;
        #pragma unroll
        for (int k = 0; k < 4; k++) cs += __ldcg(&g_clip[tid + k * 256]);
        #pragma unroll
        for (int k = 0; k < 2; k++) {
            ls += __ldcg(&g_ccl[tid + k * 256]);
            ms += __ldcg(&g_ccl[BB + tid + k * 256]);
            ks += __ldcg(&g_kl[tid + k * 256]);
        }
        blockSum4(cs, ls, ms, ks);
        if (tid == 0) {
            float clip_loss = cs / (2.f * BB);
            float bce_loss  = ls / (ms + 1e-8f);
            float kl_loss   = ks / (float)BB;
            out[0] = clip_loss + 0.5f * bce_loss + 0.3f * kl_loss;
        }
    }
}

extern "C" void kernel_launch(void* const* d_in, const int* in_sizes, int n_in,
                              void* d_out, int out_size) {
    const float* img = (const float*)d_in[0];   // logits_per_image [512,512]
    const float* txt = (const float*)d_in[1];   // logits_per_text  [512,512]
    const float* cl  = (const float*)d_in[2];   // concepts_logits  [512,256]
    const float* cis = (const float*)d_in[3];   // concepts_image_similarity [512,512]
    const int*   mc  = (const int*)d_in[4];     // medical_concepts [512,256]
    float* out = (float*)d_out;

    k1_rows<<<GRID1, 256>>>(img, txt, cl, mc);
    k2_kl  <<<GRID2, 256>>>(cis, out);
}

// round 15
// speedup vs baseline: 1.5130x; 1.3420x over previous
#include <cuda_runtime.h>
#include <math.h>

#define BB 512
#define CC 256
#define NW 8                 // 256 concepts / 32 bits
#define TEMP_INV (1.0f/0.07f)
#define GRID 512
#define NGRP 32              // completion-tree first level (16 blocks/group)

// ---- persistent scratch (no allocation allowed) ----
__device__ float    g_clip[2*BB];    // per-row (lse - diag): img [0..511], txt [512..1023]
__device__ float    g_ccl [2*BB];    // per-row bce sum [0..511], mask sum [512..1023]
__device__ float    g_kl  [BB];      // per-row KL term
__device__ unsigned g_bits[BB*NW];   // binary concept bitmasks (row-major [row][word])
__device__ float    g_warm[BB];      // digest of cis warm-touch (keeps loads alive)
__device__ unsigned g_doneA[NGRP];   // first-level completion counters (wrap -> replay-safe)
__device__ unsigned g_doneB = 0;     // second-level counter

// ---------- deterministic block reductions (256 threads) ----------
// RULE: each helper's static smem buffer must be used at most ONCE per kernel
// (no trailing __syncthreads -> reuse races).

__device__ __forceinline__ void blockMax2(float& a, float& b) {
    __shared__ float sh[2][8];
    int tid = threadIdx.x;
    #pragma unroll
    for (int o = 16; o > 0; o >>= 1) {
        a = fmaxf(a, __shfl_down_sync(0xffffffffu, a, o));
        b = fmaxf(b, __shfl_down_sync(0xffffffffu, b, o));
    }
    if ((tid & 31) == 0) { int w = tid >> 5; sh[0][w] = a; sh[1][w] = b; }
    __syncthreads();
    float ra = sh[0][0], rb = sh[1][0];
    #pragma unroll
    for (int w = 1; w < 8; w++) { ra = fmaxf(ra, sh[0][w]); rb = fmaxf(rb, sh[1][w]); }
    a = ra; b = rb;
}

__device__ __forceinline__ float blockMax1(float a) {
    __shared__ float sh[8];
    int tid = threadIdx.x;
    #pragma unroll
    for (int o = 16; o > 0; o >>= 1)
        a = fmaxf(a, __shfl_down_sync(0xffffffffu, a, o));
    if ((tid & 31) == 0) sh[tid >> 5] = a;
    __syncthreads();
    float ra = sh[0];
    #pragma unroll
    for (int w = 1; w < 8; w++) ra = fmaxf(ra, sh[w]);
    return ra;
}

__device__ __forceinline__ void blockSum3(float& a, float& b, float& c) {
    __shared__ float sh[3][8];
    int tid = threadIdx.x;
    #pragma unroll
    for (int o = 16; o > 0; o >>= 1) {
        a += __shfl_down_sync(0xffffffffu, a, o);
        b += __shfl_down_sync(0xffffffffu, b, o);
        c += __shfl_down_sync(0xffffffffu, c, o);
    }
    if ((tid & 31) == 0) { int w = tid >> 5; sh[0][w] = a; sh[1][w] = b; sh[2][w] = c; }
    __syncthreads();
    float ra = 0.f, rb = 0.f, rc = 0.f;
    #pragma unroll
    for (int w = 0; w < 8; w++) { ra += sh[0][w]; rb += sh[1][w]; rc += sh[2][w]; }
    a = ra; b = rb; c = rc;
}

__device__ __forceinline__ void blockSum4(float& a, float& b, float& c, float& d) {
    __shared__ float sh[4][8];
    int tid = threadIdx.x;
    #pragma unroll
    for (int o = 16; o > 0; o >>= 1) {
        a += __shfl_down_sync(0xffffffffu, a, o);
        b += __shfl_down_sync(0xffffffffu, b, o);
        c += __shfl_down_sync(0xffffffffu, c, o);
        d += __shfl_down_sync(0xffffffffu, d, o);
    }
    if ((tid & 31) == 0) { int w = tid >> 5; sh[0][w] = a; sh[1][w] = b; sh[2][w] = c; sh[3][w] = d; }
    __syncthreads();
    float ra = 0.f, rb = 0.f, rc = 0.f, rd = 0.f;
    #pragma unroll
    for (int w = 0; w < 8; w++) { ra += sh[0][w]; rb += sh[1][w]; rc += sh[2][w]; rd += sh[3][w]; }
    a = ra; b = rb; c = rc; d = rd;
}

// separate static buffer for the final fold (blockSum4 already used? no — but keep distinct anyway)
__device__ __forceinline__ void blockSum4b(float& a, float& b, float& c, float& d) {
    __shared__ float sh[4][8];
    int tid = threadIdx.x;
    #pragma unroll
    for (int o = 16; o > 0; o >>= 1) {
        a += __shfl_down_sync(0xffffffffu, a, o);
        b += __shfl_down_sync(0xffffffffu, b, o);
        c += __shfl_down_sync(0xffffffffu, c, o);
        d += __shfl_down_sync(0xffffffffu, d, o);
    }
    if ((tid & 31) == 0) { int w = tid >> 5; sh[0][w] = a; sh[1][w] = b; sh[2][w] = c; sh[3][w] = d; }
    __syncthreads();
    float ra = 0.f, rb = 0.f, rc = 0.f, rd = 0.f;
    #pragma unroll
    for (int w = 0; w < 8; w++) { ra += sh[0][w]; rb += sh[1][w]; rc += sh[2][w]; rd += sh[3][w]; }
    a = ra; b = rb; c = rc; d = rd;
}

// =======================================================================
// K1: per-row BCE + bitmasks + CLIP lse; warms cis row into L2.
// Exactly ONE blockMax2 + ONE blockSum4 -> no smem-buffer reuse.
// =======================================================================
__global__ void __launch_bounds__(256, 4)
k1_rows(const float* __restrict__ img,
        const float* __restrict__ txt,
        const float* __restrict__ cl,
        const int*   __restrict__ mc,
        const float* __restrict__ cis) {
    const int b   = blockIdx.x;
    const int tid = threadIdx.x;

    // issue all global loads up front (incl. cis warm-touch)
    int   m  = mc[(size_t)b * CC + tid];
    float x  = cl[(size_t)b * CC + tid];
    const float* ri = img + (size_t)b * BB;
    const float* rt = txt + (size_t)b * BB;
    float i0 = ri[tid], i1 = ri[tid + 256];
    float t0 = rt[tid], t1 = rt[tid + 256];
    float w0 = __ldcg(&cis[(size_t)b * BB + tid]);
    float w1 = __ldcg(&cis[(size_t)b * BB + tid + 256]);

    float mask = (m != -1) ? 1.f : 0.f;
    float tgt  = (m > 0)   ? 1.f : 0.f;
    float la   = (x > 0.f) ? (x + log1pf(__expf(-x))) : log1pf(__expf(x));
    float loss = (la - x * tgt) * mask;
    unsigned ball = __ballot_sync(0xffffffffu, m > 0);
    if ((tid & 31) == 0) g_bits[b * NW + (tid >> 5)] = ball;
    if (tid == 0) g_warm[b] = w0 + w1;     // keep warm loads alive (value unused)

    float mi = fmaxf(i0, i1), mt = fmaxf(t0, t1);
    blockMax2(mi, mt);
    float si = __expf(i0 - mi) + __expf(i1 - mi);
    float st = __expf(t0 - mt) + __expf(t1 - mt);
    float ls = loss, ms = mask;
    blockSum4(si, st, ls, ms);
    if (tid == 0) {
        g_clip[b]      = mi + logf(si) - ri[b];
        g_clip[BB + b] = mt + logf(st) - rt[b];
        g_ccl[b]       = ls;
        g_ccl[BB + b]  = ms;
    }
}

// =======================================================================
// K2: Jaccard -> KL per row (512 blocks, register-only, popc-only uni)
// =======================================================================
__global__ void __launch_bounds__(256, 4)
k2_kl(const float* __restrict__ cis, float* __restrict__ out) {
    const int b   = blockIdx.x;
    const int tid = threadIdx.x;
    const uint4* bits4 = (const uint4*)g_bits;   // 2 uint4 per row

    // own row's mask (broadcast loads); count from registers
    uint4 a0 = bits4[2 * b], a1 = bits4[2 * b + 1];
    int cnti = __popc(a0.x) + __popc(a0.y) + __popc(a0.z) + __popc(a0.w)
             + __popc(a1.x) + __popc(a1.y) + __popc(a1.z) + __popc(a1.w);

    // cis values (L2-warm from k1)
    float c0 = cis[(size_t)b * BB + tid];
    float c1 = cis[(size_t)b * BB + tid + 256];

    // this thread's two j bit-rows (issue early)
    uint4 p0 = bits4[2 * tid],         p1 = bits4[2 * tid + 1];
    uint4 q0 = bits4[2 * (tid + 256)], q1 = bits4[2 * (tid + 256) + 1];

    float maxc = blockMax1(fmaxf(c0, c1));
    float maxs = (cnti > 0) ? TEMP_INV : 0.f;   // sim(i,i)=1 when row nonempty

    float es = 0.f, num = 0.f, ec = 0.f;
    {
        int inter = __popc(a0.x & p0.x) + __popc(a0.y & p0.y)
                  + __popc(a0.z & p0.z) + __popc(a0.w & p0.w)
                  + __popc(a1.x & p1.x) + __popc(a1.y & p1.y)
                  + __popc(a1.z & p1.z) + __popc(a1.w & p1.w);
        int uni   = __popc(a0.x | p0.x) + __popc(a0.y | p0.y)
                  + __popc(a0.z | p0.z) + __popc(a0.w | p0.w)
                  + __popc(a1.x | p1.x) + __popc(a1.y | p1.y)
                  + __popc(a1.z | p1.z) + __popc(a1.w | p1.w);
        float sim = (uni > 0) ? (float)inter / (float)uni : 0.f;
        float s   = sim * TEMP_INV;
        float e   = __expf(s - maxs);
        es  += e;
        num += e * (s - c0);
        ec  += __expf(c0 - maxc);
    }
    {
        int inter = __popc(a0.x & q0.x) + __popc(a0.y & q0.y)
                  + __popc(a0.z & q0.z) + __popc(a0.w & q0.w)
                  + __popc(a1.x & q1.x) + __popc(a1.y & q1.y)
                  + __popc(a1.z & q1.z) + __popc(a1.w & q1.w);
        int uni   = __popc(a0.x | q0.x) + __popc(a0.y | q0.y)
                  + __popc(a0.z | q0.z) + __popc(a0.w | q0.w)
                  + __popc(a1.x | q1.x) + __popc(a1.y | q1.y)
                  + __popc(a1.z | q1.z) + __popc(a1.w | q1.w);
        float sim = (uni > 0) ? (float)inter / (float)uni : 0.f;
        float s   = sim * TEMP_INV;
        float e   = __expf(s - maxs);
        es  += e;
        num += e * (s - c1);
        ec  += __expf(c1 - maxc);
    }
    blockSum3(es, ec, num);
    if (tid == 0)
        g_kl[b] = num / es - maxs - logf(es) + maxc + logf(ec);

    // -------- two-level completion tree; last block folds -> out --------
    __shared__ bool is_last;
    __syncthreads();
    if (tid == 0) {
        __threadfence();
        unsigned t = atomicInc(&g_doneA[b >> 4], 15u);   // wraps -> replay-safe
        is_last = false;
        if (t == 15u) {
            unsigned u = atomicInc(&g_doneB, NGRP - 1);
            is_last = (u == NGRP - 1);
        }
    }
    __syncthreads();
    if (is_last) {
        __threadfence();   // acquire other blocks' writes
        float cs = 0.f, ls = 0.f, ms = 0.f, ks = 0.f;
        #pragma unroll
        for (int k = 0; k < 4; k++) cs += __ldcg(&g_clip[tid + k * 256]);
        #pragma unroll
        for (int k = 0; k < 2; k++) {
            ls += __ldcg(&g_ccl[tid + k * 256]);
            ms += __ldcg(&g_ccl[BB + tid + k * 256]);
            ks += __ldcg(&g_kl[tid + k * 256]);
        }
        blockSum4b(cs, ls, ms, ks);
        if (tid == 0) {
            float clip_loss = cs / (2.f * BB);
            float bce_loss  = ls / (ms + 1e-8f);
            float kl_loss   = ks / (float)BB;
            out[0] = clip_loss + 0.5f * bce_loss + 0.3f * kl_loss;
        }
    }
}

extern "C" void kernel_launch(void* const* d_in, const int* in_sizes, int n_in,
                              void* d_out, int out_size) {
    const float* img = (const float*)d_in[0];   // logits_per_image [512,512]
    const float* txt = (const float*)d_in[1];   // logits_per_text  [512,512]
    const float* cl  = (const float*)d_in[2];   // concepts_logits  [512,256]
    const float* cis = (const float*)d_in[3];   // concepts_image_similarity [512,512]
    const int*   mc  = (const int*)d_in[4];     // medical_concepts [512,256]
    float* out = (float*)d_out;

    k1_rows<<<GRID, 256>>>(img, txt, cl, mc, cis);
    k2_kl  <<<GRID, 256>>>(cis, out);
}